// round 1
// baseline (speedup 1.0000x reference)
#include <cuda_runtime.h>
#include <cuda_bf16.h>

// Fused separable 15x15 Gaussian blur, fp32, NHWC with C=1 (i.e. N x 1024 x 1024).
// kernel = gain * exp(-(dx^2+dy^2)/(2 s^2))  ==  [exp(-dx^2/2s^2)] (x) [gain*exp(-dy^2/2s^2)]
//
// Tile: 128 (x) by 32 (y) outputs per block, 256 threads.
// Phase 0: stage input (46 x 144) tile into smem (zero-padded at borders).
// Phase 1: horizontal 15-tap conv -> s_hz (46 x 128), 4 outputs per work item
//          from 5 LDS.128 (20-float register window).
// Phase 2: vertical 15-tap conv, one warp per 4-row output strip, float4 columns,
//          18 LDS.128 per thread feeding 4 float4 accumulators (exact 60 FMA4).

#define RAD 7
#define KS  15
#define TX  128
#define TY  32
#define HY  (TY + 2 * RAD)      // 46 rows of horizontal results
#define SIN_W 144               // staged cols: [x0-8, x0+136)
#define NTHREADS 256
#define IMG_W 1024
#define IMG_H 1024

#define SMEM_FLOATS (HY * SIN_W + HY * TX)
#define SMEM_BYTES  (SMEM_FLOATS * 4)

__global__ void __launch_bounds__(NTHREADS, 2)
gauss15_fused_kernel(const float* __restrict__ x,
                     const float* __restrict__ sigma_p,
                     const float* __restrict__ gain_p,
                     float* __restrict__ out)
{
    extern __shared__ float smem[];
    float* s_in = smem;                      // [HY][SIN_W]
    float* s_hz = smem + HY * SIN_W;         // [HY][TX]

    const int tid = threadIdx.x;
    const int x0 = blockIdx.x * TX;
    const int y0 = blockIdx.y * TY;
    const long long plane = (long long)blockIdx.z * (IMG_W * IMG_H);
    const float* img = x + plane;
    float* outp = out + plane;

    // ---- weights (all threads compute; trivial) ----
    const float s = fabsf(sigma_p[0]);
    const float g = gain_p[0];
    const float inv2s2 = 1.0f / (2.0f * s * s);
    float w[KS];
#pragma unroll
    for (int j = 0; j < KS; j++) {
        float d = (float)(j - RAD);
        w[j] = __expf(-d * d * inv2s2);
    }

    // ---- phase 0: stage input tile into smem, zero pad outside image ----
    // staged (r, c) -> global (y0 - RAD + r, x0 - 8 + c)
#pragma unroll 4
    for (int i = tid; i < HY * SIN_W; i += NTHREADS) {
        int r = i / SIN_W;
        int c = i - r * SIN_W;
        int gy = y0 - RAD + r;
        int gx = x0 - 8 + c;
        float v = 0.0f;
        if ((unsigned)gy < (unsigned)IMG_H && (unsigned)gx < (unsigned)IMG_W)
            v = img[gy * IMG_W + gx];
        s_in[i] = v;
    }
    __syncthreads();

    // ---- phase 1: horizontal conv ----
    // item -> (row r in [0,HY), col-group cg in [0,32)); outputs 4 cols: X = x0+4cg+a
    // staged index needed: 4cg+1+a+j  for j in [0,15), a in [0,4)  => window [4cg, 4cg+20)
#pragma unroll 1
    for (int item = tid; item < HY * (TX / 4); item += NTHREADS) {
        int r  = item >> 5;
        int cg = item & 31;
        const float* rowp = s_in + r * SIN_W + cg * 4;
        float v[20];
#pragma unroll
        for (int k = 0; k < 5; k++) {
            float4 t = *(const float4*)(rowp + 4 * k);
            v[4 * k + 0] = t.x; v[4 * k + 1] = t.y;
            v[4 * k + 2] = t.z; v[4 * k + 3] = t.w;
        }
        float o0 = 0.f, o1 = 0.f, o2 = 0.f, o3 = 0.f;
#pragma unroll
        for (int j = 0; j < KS; j++) {
            o0 = fmaf(w[j], v[1 + j], o0);
            o1 = fmaf(w[j], v[2 + j], o1);
            o2 = fmaf(w[j], v[3 + j], o2);
            o3 = fmaf(w[j], v[4 + j], o3);
        }
        float* hzp = s_hz + r * TX + cg * 4;
        hzp[0] = o0; hzp[1] = o1; hzp[2] = o2; hzp[3] = o3;
    }
    __syncthreads();

    // ---- phase 2: vertical conv ----
    // thread -> (cg in [0,32), strip ys in [0,8)); outputs rows ob..ob+3 (ob = 4*ys)
    // output row (rel) oy needs hz rows oy .. oy+14; for the strip: rows ob .. ob+17
    {
        const int cg = tid & 31;
        const int ys = tid >> 5;
        const int ob = ys * 4;

        float4 a0 = {0.f, 0.f, 0.f, 0.f};
        float4 a1 = {0.f, 0.f, 0.f, 0.f};
        float4 a2 = {0.f, 0.f, 0.f, 0.f};
        float4 a3 = {0.f, 0.f, 0.f, 0.f};

#pragma unroll
        for (int t = 0; t < KS + 3; t++) {           // 18 hz rows
            float4 v = *(const float4*)(s_hz + (ob + t) * TX + cg * 4);
            if (t - 0 >= 0 && t - 0 < KS) {
                float wj = w[t - 0];
                a0.x = fmaf(wj, v.x, a0.x); a0.y = fmaf(wj, v.y, a0.y);
                a0.z = fmaf(wj, v.z, a0.z); a0.w = fmaf(wj, v.w, a0.w);
            }
            if (t - 1 >= 0 && t - 1 < KS) {
                float wj = w[t - 1];
                a1.x = fmaf(wj, v.x, a1.x); a1.y = fmaf(wj, v.y, a1.y);
                a1.z = fmaf(wj, v.z, a1.z); a1.w = fmaf(wj, v.w, a1.w);
            }
            if (t - 2 >= 0 && t - 2 < KS) {
                float wj = w[t - 2];
                a2.x = fmaf(wj, v.x, a2.x); a2.y = fmaf(wj, v.y, a2.y);
                a2.z = fmaf(wj, v.z, a2.z); a2.w = fmaf(wj, v.w, a2.w);
            }
            if (t - 3 >= 0 && t - 3 < KS) {
                float wj = w[t - 3];
                a3.x = fmaf(wj, v.x, a3.x); a3.y = fmaf(wj, v.y, a3.y);
                a3.z = fmaf(wj, v.z, a3.z); a3.w = fmaf(wj, v.w, a3.w);
            }
        }

        // apply gain once
        a0.x *= g; a0.y *= g; a0.z *= g; a0.w *= g;
        a1.x *= g; a1.y *= g; a1.z *= g; a1.w *= g;
        a2.x *= g; a2.y *= g; a2.z *= g; a2.w *= g;
        a3.x *= g; a3.y *= g; a3.z *= g; a3.w *= g;

        float* o = outp + (y0 + ob) * IMG_W + x0 + cg * 4;
        *(float4*)(o + 0 * IMG_W) = a0;
        *(float4*)(o + 1 * IMG_W) = a1;
        *(float4*)(o + 2 * IMG_W) = a2;
        *(float4*)(o + 3 * IMG_W) = a3;
    }
}

extern "C" void kernel_launch(void* const* d_in, const int* in_sizes, int n_in,
                              void* d_out, int out_size)
{
    const float* x     = (const float*)d_in[0];
    const float* sigma = (const float*)d_in[1];
    const float* gain  = (const float*)d_in[2];
    float* out = (float*)d_out;

    int nimg = in_sizes[0] / (IMG_W * IMG_H);

    cudaFuncSetAttribute(gauss15_fused_kernel,
                         cudaFuncAttributeMaxDynamicSharedMemorySize, SMEM_BYTES);

    dim3 grid(IMG_W / TX, IMG_H / TY, nimg);
    gauss15_fused_kernel<<<grid, NTHREADS, SMEM_BYTES>>>(x, sigma, gain, out);
}

// round 3
// speedup vs baseline: 1.5869x; 1.5869x over previous
#include <cuda_runtime.h>
#include <cuda_bf16.h>

// Fused separable 15x15 Gaussian blur, fp32, N x 1024 x 1024 (NHWC, C=1).
// kernel = gain * exp(-(dx^2+dy^2)/(2 s^2)) = outer(exp(-dy^2/2s^2), exp(-dx^2/2s^2)) * gain
//
// R3 = R2 with the phase-2 smem row-stride unit bug fixed:
//  row t of s_hz is TX=128 floats = 32 ulonglong2 (was wrongly 64 -> OOB).
//  Also force 16B alignment on s_hz for the vector LDS.

#define RAD 7
#define KS  15
#define TX  128
#define TY  64
#define HYP 80                 // 78 needed rows padded to 80 (trip count 2560/512 = 5)
#define NTHREADS 512
#define IMG_W 1024
#define IMG_H 1024

typedef unsigned long long ull;

__device__ __forceinline__ ull pack2(float a, float b) {
    ull r;
    asm("mov.b64 %0, {%1, %2};" : "=l"(r) : "f"(a), "f"(b));
    return r;
}
__device__ __forceinline__ ull ffma2(ull a, ull b, ull c) {
    ull d;
    asm("fma.rn.f32x2 %0, %1, %2, %3;" : "=l"(d) : "l"(a), "l"(b), "l"(c));
    return d;
}
__device__ __forceinline__ ull fmul2(ull a, ull b) {
    ull d;
    asm("mul.rn.f32x2 %0, %1, %2;" : "=l"(d) : "l"(a), "l"(b));
    return d;
}

__global__ void __launch_bounds__(NTHREADS, 2)
gauss15_fused2_kernel(const float* __restrict__ x,
                      const float* __restrict__ sigma_p,
                      const float* __restrict__ gain_p,
                      float* __restrict__ out)
{
    __shared__ alignas(16) float s_hz[HYP * TX];   // 40 KB

    const int tid = threadIdx.x;
    const int x0 = blockIdx.x * TX;
    const int y0 = blockIdx.y * TY;
    const long long plane = (long long)blockIdx.z * (IMG_W * IMG_H);
    const float* img = x + plane;
    float* outp = out + plane;

    // ---- weights: 8 distinct scalars (symmetric), all threads compute ----
    const float s = fabsf(sigma_p[0]);
    const float g = gain_p[0];
    const float inv2s2 = 1.0f / (2.0f * s * s);
    float ws[8];
#pragma unroll
    for (int j = 0; j < 8; j++) {
        float d = (float)(j - RAD);
        ws[j] = __expf(-d * d * inv2s2);
    }
#define WJ(j) ws[((j) <= 7) ? (j) : (14 - (j))]

    // ---- phase 1: horizontal conv, direct from global ----
    // cg = tid & 31 (invariant), r = (tid>>5) + 16*it, it in [0,5).
    // window gx in [x0-8+4cg, x0-8+4cg+20), 5 aligned float4 chunks.
    {
        const int cg = tid & 31;
        const int r0 = tid >> 5;
        const int gxb = x0 - 8 + cg * 4;            // first chunk's gx
        const float* rowp0 = img + (long long)(y0 - RAD + r0) * IMG_W + gxb;
        float* hzp0 = s_hz + r0 * TX + cg * 4;

        // per-chunk x validity is row-independent and it-invariant
        bool cvx[5];
#pragma unroll
        for (int k = 0; k < 5; k++) {
            int gx = gxb + 4 * k;
            cvx[k] = (gx >= 0) && (gx < IMG_W);
        }

#pragma unroll
        for (int it = 0; it < 5; it++) {
            const int r = r0 + 16 * it;
            const int gy = y0 - RAD + r;
            const bool rv = ((unsigned)gy < (unsigned)IMG_H);
            const float* rowp = rowp0 + (long long)(16 * it) * IMG_W;

            float v[20];
#pragma unroll
            for (int k = 0; k < 5; k++) {
                float4 t = make_float4(0.f, 0.f, 0.f, 0.f);
                if (rv && cvx[k]) t = *(const float4*)(rowp + 4 * k);
                v[4 * k + 0] = t.x; v[4 * k + 1] = t.y;
                v[4 * k + 2] = t.z; v[4 * k + 3] = t.w;
            }
            float o0 = 0.f, o1 = 0.f, o2 = 0.f, o3 = 0.f;
#pragma unroll
            for (int j = 0; j < KS; j++) {
                float wj = WJ(j);
                o0 = fmaf(wj, v[1 + j], o0);
                o1 = fmaf(wj, v[2 + j], o1);
                o2 = fmaf(wj, v[3 + j], o2);
                o3 = fmaf(wj, v[4 + j], o3);
            }
            float4* hzp = (float4*)(hzp0 + 16 * it * TX);
            *hzp = make_float4(o0, o1, o2, o3);
        }
    }
    __syncthreads();

    // ---- phase 2: vertical conv with packed f32x2 ----
    // thread -> (cg in [0,32), strip ys in [0,16)), outputs rows ob..ob+3.
    {
        const int cg = tid & 31;
        const int ys = tid >> 5;
        const int ob = ys * 4;

        ull wv[8];
#pragma unroll
        for (int j = 0; j < 8; j++) wv[j] = pack2(ws[j], ws[j]);
#define WV(j) wv[((j) <= 7) ? (j) : (14 - (j))]

        ull acc[8];                           // rows k=0..3 x {xy, zw}
#pragma unroll
        for (int i = 0; i < 8; i++) acc[i] = 0ull;

        // row t of s_hz = TX floats = TX/4 ulonglong2 (16B) elements
        const ulonglong2* hzbase =
            (const ulonglong2*)(s_hz + ob * TX + cg * 4);
#pragma unroll
        for (int t = 0; t < KS + 3; t++) {    // hz rows ob .. ob+17
            ulonglong2 v = hzbase[t * (TX / 4)];
#pragma unroll
            for (int k = 0; k < 4; k++) {
                if (t >= k && t - k < KS) {
                    ull wp = WV(t - k);
                    acc[2 * k + 0] = ffma2(wp, v.x, acc[2 * k + 0]);
                    acc[2 * k + 1] = ffma2(wp, v.y, acc[2 * k + 1]);
                }
            }
        }

        const ull gp = pack2(g, g);
        float* o = outp + (long long)(y0 + ob) * IMG_W + x0 + cg * 4;
#pragma unroll
        for (int k = 0; k < 4; k++) {
            ulonglong2 r;
            r.x = fmul2(acc[2 * k + 0], gp);
            r.y = fmul2(acc[2 * k + 1], gp);
            *(ulonglong2*)(o + (long long)k * IMG_W) = r;
        }
    }
}

extern "C" void kernel_launch(void* const* d_in, const int* in_sizes, int n_in,
                              void* d_out, int out_size)
{
    const float* x     = (const float*)d_in[0];
    const float* sigma = (const float*)d_in[1];
    const float* gain  = (const float*)d_in[2];
    float* out = (float*)d_out;

    int nimg = in_sizes[0] / (IMG_W * IMG_H);

    dim3 grid(IMG_W / TX, IMG_H / TY, nimg);
    gauss15_fused2_kernel<<<grid, NTHREADS>>>(x, sigma, gain, out);
}